// round 12
// baseline (speedup 1.0000x reference)
#include <cuda_runtime.h>
#include <cstdint>

#define N_NODES 4096
#define F_IN    512
#define HD1     64
#define NH1     8
#define C2      16
#define MAXDEG  256

__device__ int   g_nbr[N_NODES * MAXDEG];
__device__ int   g_deg[N_NODES];
__device__ float g_h1 [N_NODES * HD1];
__device__ float g_es1[N_NODES * NH1];
__device__ float g_ed1[N_NODES * NH1];
__device__ float g_h2 [N_NODES * C2];
__device__ float g_es2[N_NODES];
__device__ float g_ed2[N_NODES];

// ---------------------------------------------------------------------------
// K1: adjacency scan -> neighbor lists (unchanged, measured-best shape).
// ---------------------------------------------------------------------------
__global__ __launch_bounds__(128) void k_scan(const void* __restrict__ adj)
{
    const int i    = blockIdx.x;
    const int tid  = threadIdx.x;
    const int lane = tid & 31;
    const int wid  = tid >> 5;
    const uint8_t* u8 = (const uint8_t*)adj;

    int fmt;
    if (u8[(size_t)N_NODES + 1] == 1)            fmt = 0;
    else if (u8[4 * ((size_t)N_NODES + 1)] == 1) fmt = 1;
    else                                         fmt = 2;

    uint32_t mask = 0;
    #pragma unroll
    for (int r = 0; r < 8; r++) {
        const int cbase = (r * 128 + tid) * 4;
        uint32_t p0, p1, p2, p3;
        if (fmt == 2) {
            float4 v = *(const float4*)((const float*)adj + (size_t)i * N_NODES + cbase);
            p0 = v.x != 0.f; p1 = v.y != 0.f; p2 = v.z != 0.f; p3 = v.w != 0.f;
        } else if (fmt == 1) {
            int4 v = *(const int4*)((const int*)adj + (size_t)i * N_NODES + cbase);
            p0 = v.x != 0; p1 = v.y != 0; p2 = v.z != 0; p3 = v.w != 0;
        } else {
            uint32_t w = *(const uint32_t*)(u8 + (size_t)i * N_NODES + cbase);
            p0 = (w & 0x000000FFu) != 0;
            p1 = (w & 0x0000FF00u) != 0;
            p2 = (w & 0x00FF0000u) != 0;
            p3 = (w & 0xFF000000u) != 0;
        }
        mask |= (p0 << (r * 4)) | (p1 << (r * 4 + 1)) |
                (p2 << (r * 4 + 2)) | (p3 << (r * 4 + 3));
    }
    const int cnt = __popc(mask);

    int incl = cnt;
    #pragma unroll
    for (int o = 1; o < 32; o <<= 1) {
        int t = __shfl_up_sync(0xFFFFFFFFu, incl, o);
        if (lane >= o) incl += t;
    }
    __shared__ int wsum[4];
    if (lane == 31) wsum[wid] = incl;
    __syncthreads();
    int wpre = 0, total = 0;
    #pragma unroll
    for (int wq = 0; wq < 4; wq++) {
        int t = wsum[wq];
        if (wq < wid) wpre += t;
        total += t;
    }
    if (tid == 0) g_deg[i] = (total > MAXDEG) ? MAXDEG : total;

    int base = wpre + (incl - cnt);
    int* out = g_nbr + (size_t)i * MAXDEG;
    #pragma unroll
    for (int r = 0; r < 8; r++) {
        const int cbase = (r * 128 + tid) * 4;
        #pragma unroll
        for (int q = 0; q < 4; q++) {
            if ((mask >> (r * 4 + q)) & 1u) {
                if (base < MAXDEG) out[base] = cbase + q;
                base++;
            }
        }
    }
}

// ---------------------------------------------------------------------------
// K2: GEMM1 h1 = x @ W1 + fused es1/ed1 epilogue. Double-buffered (unchanged).
// ---------------------------------------------------------------------------
__global__ __launch_bounds__(256) void k_gemm1(const float* __restrict__ X,
                                               const float* __restrict__ W,
                                               const float* __restrict__ a_src,
                                               const float* __restrict__ a_dst)
{
    __shared__ float As[2][32][33];
    __shared__ float Bs[2][32][64];

    const int tid = threadIdx.x;
    const int tx  = tid & 15;
    const int ty  = tid >> 4;
    const int m0  = blockIdx.x * 32;

    const int ar  = tid >> 3;
    const int ac4 = tid & 7;
    const int br  = tid >> 4;
    const int bc4 = tid & 15;

    float acc[2][4] = {};

    {
        float4 va = *(const float4*)(X + (size_t)(m0 + ar) * F_IN + ac4 * 4);
        As[0][ac4 * 4 + 0][ar] = va.x;
        As[0][ac4 * 4 + 1][ar] = va.y;
        As[0][ac4 * 4 + 2][ar] = va.z;
        As[0][ac4 * 4 + 3][ar] = va.w;
        float4 vb0 = *(const float4*)(W + (size_t)br * HD1 + bc4 * 4);
        float4 vb1 = *(const float4*)(W + (size_t)(br + 16) * HD1 + bc4 * 4);
        *(float4*)(&Bs[0][br][bc4 * 4])      = vb0;
        *(float4*)(&Bs[0][br + 16][bc4 * 4]) = vb1;
    }
    __syncthreads();

    #pragma unroll 1
    for (int t = 0; t < 16; t++) {
        const int cur = t & 1;
        const int nxt = cur ^ 1;

        float4 va, vb0, vb1;
        if (t < 15) {
            const int kt = (t + 1) * 32;
            va  = *(const float4*)(X + (size_t)(m0 + ar) * F_IN + kt + ac4 * 4);
            vb0 = *(const float4*)(W + (size_t)(kt + br) * HD1 + bc4 * 4);
            vb1 = *(const float4*)(W + (size_t)(kt + br + 16) * HD1 + bc4 * 4);
        }

        #pragma unroll
        for (int k = 0; k < 32; k++) {
            float a0 = As[cur][k][ty * 2 + 0];
            float a1 = As[cur][k][ty * 2 + 1];
            float4 b = *(const float4*)(&Bs[cur][k][tx * 4]);
            acc[0][0] += a0 * b.x; acc[0][1] += a0 * b.y;
            acc[0][2] += a0 * b.z; acc[0][3] += a0 * b.w;
            acc[1][0] += a1 * b.x; acc[1][1] += a1 * b.y;
            acc[1][2] += a1 * b.z; acc[1][3] += a1 * b.w;
        }

        if (t < 15) {
            As[nxt][ac4 * 4 + 0][ar] = va.x;
            As[nxt][ac4 * 4 + 1][ar] = va.y;
            As[nxt][ac4 * 4 + 2][ar] = va.z;
            As[nxt][ac4 * 4 + 3][ar] = va.w;
            *(float4*)(&Bs[nxt][br][bc4 * 4])      = vb0;
            *(float4*)(&Bs[nxt][br + 16][bc4 * 4]) = vb1;
        }
        __syncthreads();
    }

    #pragma unroll
    for (int u = 0; u < 2; u++) {
        float4 v = make_float4(acc[u][0], acc[u][1], acc[u][2], acc[u][3]);
        *(float4*)(g_h1 + (size_t)(m0 + ty * 2 + u) * HD1 + tx * 4) = v;
    }

    float4 ws = *(const float4*)(a_src + tx * 4);
    float4 wd = *(const float4*)(a_dst + tx * 4);
    float s0 = acc[0][0]*ws.x + acc[0][1]*ws.y + acc[0][2]*ws.z + acc[0][3]*ws.w;
    float s1 = acc[1][0]*ws.x + acc[1][1]*ws.y + acc[1][2]*ws.z + acc[1][3]*ws.w;
    float d0 = acc[0][0]*wd.x + acc[0][1]*wd.y + acc[0][2]*wd.z + acc[0][3]*wd.w;
    float d1 = acc[1][0]*wd.x + acc[1][1]*wd.y + acc[1][2]*wd.z + acc[1][3]*wd.w;
    s0 += __shfl_xor_sync(0xFFFFFFFFu, s0, 1);
    s1 += __shfl_xor_sync(0xFFFFFFFFu, s1, 1);
    d0 += __shfl_xor_sync(0xFFFFFFFFu, d0, 1);
    d1 += __shfl_xor_sync(0xFFFFFFFFu, d1, 1);
    if ((tx & 1) == 0) {
        int h = tx >> 1;
        g_es1[(m0 + ty * 2 + 0) * NH1 + h] = s0;
        g_es1[(m0 + ty * 2 + 1) * NH1 + h] = s1;
        g_ed1[(m0 + ty * 2 + 0) * NH1 + h] = d0;
        g_ed1[(m0 + ty * 2 + 1) * NH1 + h] = d1;
    }
}

// ---------------------------------------------------------------------------
// K3: layer-1 attention + ELU + fused layer-2 projection & scores.
// SINGLE-PASS: thread = column c (head h=c>>3). Per neighbor: compute
// w = exp(lrelu(es+ed)) inline (broadcast loads), accumulate w*h1 and sum(w).
// No ew array, no reduction phases, 2 barriers total.
// ---------------------------------------------------------------------------
__global__ __launch_bounds__(64) void k_attn1(const float* __restrict__ W2,
                                              const float* __restrict__ a2_src,
                                              const float* __restrict__ a2_dst)
{
    const int i   = blockIdx.x;
    const int tid = threadIdx.x;       // output column c
    const int h   = tid >> 3;          // head
    const int deg = g_deg[i];

    __shared__ int   snbr[MAXDEG];
    __shared__ float sa1[HD1];

    for (int j = tid; j < deg; j += 64)
        snbr[j] = g_nbr[(size_t)i * MAXDEG + j];
    __syncthreads();

    const float esi = g_es1[i * NH1 + h];   // broadcast within head group

    float a0 = 0.f, a1 = 0.f, a2 = 0.f, a3 = 0.f;
    float s0 = 0.f, s1 = 0.f, s2 = 0.f, s3 = 0.f;
    int j = 0;
    for (; j + 4 <= deg; j += 4) {
        const int n0 = snbr[j+0], n1 = snbr[j+1], n2 = snbr[j+2], n3 = snbr[j+3];
        float e0 = esi + g_ed1[n0 * NH1 + h];
        float e1 = esi + g_ed1[n1 * NH1 + h];
        float e2 = esi + g_ed1[n2 * NH1 + h];
        float e3 = esi + g_ed1[n3 * NH1 + h];
        e0 = (e0 > 0.f) ? e0 : 0.2f * e0;
        e1 = (e1 > 0.f) ? e1 : 0.2f * e1;
        e2 = (e2 > 0.f) ? e2 : 0.2f * e2;
        e3 = (e3 > 0.f) ? e3 : 0.2f * e3;
        float w0 = __expf(e0), w1 = __expf(e1), w2 = __expf(e2), w3 = __expf(e3);
        a0 += w0 * g_h1[(size_t)n0 * HD1 + tid];  s0 += w0;
        a1 += w1 * g_h1[(size_t)n1 * HD1 + tid];  s1 += w1;
        a2 += w2 * g_h1[(size_t)n2 * HD1 + tid];  s2 += w2;
        a3 += w3 * g_h1[(size_t)n3 * HD1 + tid];  s3 += w3;
    }
    for (; j < deg; j++) {
        const int n = snbr[j];
        float e = esi + g_ed1[n * NH1 + h];
        e = (e > 0.f) ? e : 0.2f * e;
        float w = __expf(e);
        a0 += w * g_h1[(size_t)n * HD1 + tid];
        s0 += w;
    }
    const float acc  = (a0 + a1) + (a2 + a3);
    const float wsum = (s0 + s1) + (s2 + s3);
    float v = acc / wsum;
    v = (v > 0.f) ? v : expm1f(v);   // ELU
    sa1[tid] = v;
    __syncthreads();

    // fused layer-2 row: h2[i,:] = sa1 @ W2 (64x16) + es2/ed2
    if (tid < C2) {
        float vv = 0.f;
        #pragma unroll 8
        for (int k = 0; k < HD1; k++)
            vv += sa1[k] * __ldg(&W2[k * C2 + tid]);
        g_h2[(size_t)i * C2 + tid] = vv;

        float s = vv * a2_src[tid];
        float d = vv * a2_dst[tid];
        #pragma unroll
        for (int o = 8; o >= 1; o >>= 1) {
            s += __shfl_xor_sync(0x0000FFFFu, s, o);
            d += __shfl_xor_sync(0x0000FFFFu, d, o);
        }
        if (tid == 0) {
            g_es2[i] = s;
            g_ed2[i] = d;
        }
    }
}

// ---------------------------------------------------------------------------
// K4: layer-2 sparse attention. Single fused pass (round-11 best, unchanged).
// ---------------------------------------------------------------------------
__global__ __launch_bounds__(256) void k_attn2(float* __restrict__ out)
{
    const int w    = threadIdx.x >> 5;
    const int lane = threadIdx.x & 31;
    const int i    = blockIdx.x * 8 + w;
    const int deg  = g_deg[i];

    __shared__ int snbr[8][MAXDEG];

    for (int j = lane; j < deg; j += 32)
        snbr[w][j] = g_nbr[(size_t)i * MAXDEG + j];
    __syncwarp();

    const float esi = g_es2[i];
    const int g  = lane >> 2;
    const int c4 = lane & 3;

    float4 acc = make_float4(0.f, 0.f, 0.f, 0.f);
    float  wsum = 0.f;
    for (int base = 0; base < deg; base += 8) {
        int j = base + g;
        if (j < deg) {
            int   n  = snbr[w][j];
            float e  = esi + g_ed2[n];
            e = (e > 0.f) ? e : 0.2f * e;
            float wt = __expf(e);
            float4 v = *(const float4*)(g_h2 + (size_t)n * C2 + c4 * 4);
            acc.x += wt * v.x;
            acc.y += wt * v.y;
            acc.z += wt * v.z;
            acc.w += wt * v.w;
            wsum  += wt;
        }
    }
    #pragma unroll
    for (int o = 4; o <= 16; o <<= 1) {
        acc.x += __shfl_xor_sync(0xFFFFFFFFu, acc.x, o);
        acc.y += __shfl_xor_sync(0xFFFFFFFFu, acc.y, o);
        acc.z += __shfl_xor_sync(0xFFFFFFFFu, acc.z, o);
        acc.w += __shfl_xor_sync(0xFFFFFFFFu, acc.w, o);
        wsum  += __shfl_xor_sync(0xFFFFFFFFu, wsum,  o);
    }
    if (lane < 4) {
        const float inv = 1.f / wsum;
        float4 r = make_float4(acc.x * inv, acc.y * inv, acc.z * inv, acc.w * inv);
        *(float4*)(out + (size_t)i * C2 + lane * 4) = r;
    }
}

// ---------------------------------------------------------------------------
// Launch: strictly sequential on the capture stream.
// ---------------------------------------------------------------------------
extern "C" void kernel_launch(void* const* d_in, const int* in_sizes, int n_in,
                              void* d_out, int out_size)
{
    const float* x      = (const float*)d_in[0];
    const void*  adj    = d_in[1];
    const float* W1     = (const float*)d_in[2];
    const float* a1_src = (const float*)d_in[3];
    const float* a1_dst = (const float*)d_in[4];
    const float* W2     = (const float*)d_in[5];
    const float* a2_src = (const float*)d_in[6];
    const float* a2_dst = (const float*)d_in[7];
    float* out = (float*)d_out;

    k_scan <<<N_NODES, 128>>>(adj);
    k_gemm1<<<N_NODES / 32, 256>>>(x, W1, a1_src, a1_dst);
    k_attn1<<<N_NODES, 64>>>(W2, a2_src, a2_dst);
    k_attn2<<<N_NODES / 8, 256>>>(out);
}

// round 13
// speedup vs baseline: 1.0285x; 1.0285x over previous
#include <cuda_runtime.h>
#include <cstdint>

#define N_NODES 4096
#define F_IN    512
#define HD1     64
#define NH1     8
#define C2      16
#define MAXDEG  256

__device__ int   g_nbr[N_NODES * MAXDEG];
__device__ int   g_deg[N_NODES];
__device__ float g_h1 [N_NODES * HD1];
__device__ float g_es1[N_NODES * NH1];
__device__ float g_ed1[N_NODES * NH1];
__device__ float g_h2 [N_NODES * C2];
__device__ float g_es2[N_NODES];
__device__ float g_ed2[N_NODES];

// ---------------------------------------------------------------------------
// K1: GEMM1 h1 = x @ W1 + fused es1/ed1 epilogue. Double-buffered (unchanged,
// measured-best).
// ---------------------------------------------------------------------------
__global__ __launch_bounds__(256) void k_gemm1(const float* __restrict__ X,
                                               const float* __restrict__ W,
                                               const float* __restrict__ a_src,
                                               const float* __restrict__ a_dst)
{
    __shared__ float As[2][32][33];
    __shared__ float Bs[2][32][64];

    const int tid = threadIdx.x;
    const int tx  = tid & 15;
    const int ty  = tid >> 4;
    const int m0  = blockIdx.x * 32;

    const int ar  = tid >> 3;
    const int ac4 = tid & 7;
    const int br  = tid >> 4;
    const int bc4 = tid & 15;

    float acc[2][4] = {};

    {
        float4 va = *(const float4*)(X + (size_t)(m0 + ar) * F_IN + ac4 * 4);
        As[0][ac4 * 4 + 0][ar] = va.x;
        As[0][ac4 * 4 + 1][ar] = va.y;
        As[0][ac4 * 4 + 2][ar] = va.z;
        As[0][ac4 * 4 + 3][ar] = va.w;
        float4 vb0 = *(const float4*)(W + (size_t)br * HD1 + bc4 * 4);
        float4 vb1 = *(const float4*)(W + (size_t)(br + 16) * HD1 + bc4 * 4);
        *(float4*)(&Bs[0][br][bc4 * 4])      = vb0;
        *(float4*)(&Bs[0][br + 16][bc4 * 4]) = vb1;
    }
    __syncthreads();

    #pragma unroll 1
    for (int t = 0; t < 16; t++) {
        const int cur = t & 1;
        const int nxt = cur ^ 1;

        float4 va, vb0, vb1;
        if (t < 15) {
            const int kt = (t + 1) * 32;
            va  = *(const float4*)(X + (size_t)(m0 + ar) * F_IN + kt + ac4 * 4);
            vb0 = *(const float4*)(W + (size_t)(kt + br) * HD1 + bc4 * 4);
            vb1 = *(const float4*)(W + (size_t)(kt + br + 16) * HD1 + bc4 * 4);
        }

        #pragma unroll
        for (int k = 0; k < 32; k++) {
            float a0 = As[cur][k][ty * 2 + 0];
            float a1 = As[cur][k][ty * 2 + 1];
            float4 b = *(const float4*)(&Bs[cur][k][tx * 4]);
            acc[0][0] += a0 * b.x; acc[0][1] += a0 * b.y;
            acc[0][2] += a0 * b.z; acc[0][3] += a0 * b.w;
            acc[1][0] += a1 * b.x; acc[1][1] += a1 * b.y;
            acc[1][2] += a1 * b.z; acc[1][3] += a1 * b.w;
        }

        if (t < 15) {
            As[nxt][ac4 * 4 + 0][ar] = va.x;
            As[nxt][ac4 * 4 + 1][ar] = va.y;
            As[nxt][ac4 * 4 + 2][ar] = va.z;
            As[nxt][ac4 * 4 + 3][ar] = va.w;
            *(float4*)(&Bs[nxt][br][bc4 * 4])      = vb0;
            *(float4*)(&Bs[nxt][br + 16][bc4 * 4]) = vb1;
        }
        __syncthreads();
    }

    #pragma unroll
    for (int u = 0; u < 2; u++) {
        float4 v = make_float4(acc[u][0], acc[u][1], acc[u][2], acc[u][3]);
        *(float4*)(g_h1 + (size_t)(m0 + ty * 2 + u) * HD1 + tx * 4) = v;
    }

    float4 ws = *(const float4*)(a_src + tx * 4);
    float4 wd = *(const float4*)(a_dst + tx * 4);
    float s0 = acc[0][0]*ws.x + acc[0][1]*ws.y + acc[0][2]*ws.z + acc[0][3]*ws.w;
    float s1 = acc[1][0]*ws.x + acc[1][1]*ws.y + acc[1][2]*ws.z + acc[1][3]*ws.w;
    float d0 = acc[0][0]*wd.x + acc[0][1]*wd.y + acc[0][2]*wd.z + acc[0][3]*wd.w;
    float d1 = acc[1][0]*wd.x + acc[1][1]*wd.y + acc[1][2]*wd.z + acc[1][3]*wd.w;
    s0 += __shfl_xor_sync(0xFFFFFFFFu, s0, 1);
    s1 += __shfl_xor_sync(0xFFFFFFFFu, s1, 1);
    d0 += __shfl_xor_sync(0xFFFFFFFFu, d0, 1);
    d1 += __shfl_xor_sync(0xFFFFFFFFu, d1, 1);
    if ((tx & 1) == 0) {
        int h = tx >> 1;
        g_es1[(m0 + ty * 2 + 0) * NH1 + h] = s0;
        g_es1[(m0 + ty * 2 + 1) * NH1 + h] = s1;
        g_ed1[(m0 + ty * 2 + 0) * NH1 + h] = d0;
        g_ed1[(m0 + ty * 2 + 1) * NH1 + h] = d1;
    }
}

// ---------------------------------------------------------------------------
// K2: FUSED adjacency-scan + layer-1 attention + ELU + layer-2 row + scores.
// 1 block/row, 64 threads. Homogeneous fusion: every block scans its own
// adjacency row (cross-block pipelining hides the DRAM scan behind other
// blocks' gather phases), builds the neighbor list (also written to g_nbr
// for attn2), then runs the round-11 two-pass no-max softmax attention.
// ---------------------------------------------------------------------------
__global__ __launch_bounds__(64) void k_attn1(const void* __restrict__ adj,
                                              const float* __restrict__ W2,
                                              const float* __restrict__ a2_src,
                                              const float* __restrict__ a2_dst)
{
    const int i    = blockIdx.x;
    const int tid  = threadIdx.x;
    const int lane = tid & 31;
    const int wid  = tid >> 5;
    const uint8_t* u8 = (const uint8_t*)adj;

    __shared__ int   snbr[MAXDEG];
    __shared__ float ew[MAXDEG * NH1];
    __shared__ float red[2][NH1];
    __shared__ float ssv[NH1];
    __shared__ float sa1[HD1];
    __shared__ int   wsum[2];

    // ---- phase 0: scan adjacency row i (64 cols/thread, 16 float4 rounds) ----
    int fmt;
    if (u8[(size_t)N_NODES + 1] == 1)            fmt = 0;
    else if (u8[4 * ((size_t)N_NODES + 1)] == 1) fmt = 1;
    else                                         fmt = 2;

    uint64_t mask = 0;
    #pragma unroll
    for (int r = 0; r < 16; r++) {
        const int cbase = (r * 64 + tid) * 4;
        uint64_t p0, p1, p2, p3;
        if (fmt == 2) {
            float4 v = *(const float4*)((const float*)adj + (size_t)i * N_NODES + cbase);
            p0 = v.x != 0.f; p1 = v.y != 0.f; p2 = v.z != 0.f; p3 = v.w != 0.f;
        } else if (fmt == 1) {
            int4 v = *(const int4*)((const int*)adj + (size_t)i * N_NODES + cbase);
            p0 = v.x != 0; p1 = v.y != 0; p2 = v.z != 0; p3 = v.w != 0;
        } else {
            uint32_t w = *(const uint32_t*)(u8 + (size_t)i * N_NODES + cbase);
            p0 = (w & 0x000000FFu) != 0;
            p1 = (w & 0x0000FF00u) != 0;
            p2 = (w & 0x00FF0000u) != 0;
            p3 = (w & 0xFF000000u) != 0;
        }
        mask |= (p0 << (r * 4)) | (p1 << (r * 4 + 1)) |
                (p2 << (r * 4 + 2)) | (p3 << (r * 4 + 3));
    }
    const int cnt = (int)__popcll(mask);

    int incl = cnt;
    #pragma unroll
    for (int o = 1; o < 32; o <<= 1) {
        int t = __shfl_up_sync(0xFFFFFFFFu, incl, o);
        if (lane >= o) incl += t;
    }
    if (lane == 31) wsum[wid] = incl;
    __syncthreads();
    const int total = wsum[0] + wsum[1];
    const int deg   = (total > MAXDEG) ? MAXDEG : total;
    if (tid == 0) g_deg[i] = deg;

    {
        int base = ((wid == 1) ? wsum[0] : 0) + (incl - cnt);
        int* gout = g_nbr + (size_t)i * MAXDEG;
        #pragma unroll
        for (int r = 0; r < 16; r++) {
            const int cbase = (r * 64 + tid) * 4;
            #pragma unroll
            for (int q = 0; q < 4; q++) {
                if ((mask >> (r * 4 + q)) & 1ull) {
                    if (base < MAXDEG) {
                        snbr[base] = cbase + q;
                        gout[base] = cbase + q;   // for k_attn2
                    }
                    base++;
                }
            }
        }
    }
    __syncthreads();

    // ---- phase 1: fill w = exp(leakyrelu(e)) + sum partials (round-11) ----
    const int h  = tid & 7;
    const int wh = tid >> 5;
    const int tot = deg * NH1;
    const float esi_h = g_es1[i * NH1 + h];

    float sloc = 0.f;
    for (int idx = tid; idx < tot; idx += 64) {
        int j = idx >> 3;
        float e = esi_h + g_ed1[snbr[j] * NH1 + h];
        e = (e > 0.f) ? e : 0.2f * e;
        float w = __expf(e);
        ew[idx] = w;
        sloc += w;
    }
    sloc += __shfl_xor_sync(0xFFFFFFFFu, sloc, 8);
    sloc += __shfl_xor_sync(0xFFFFFFFFu, sloc, 16);
    if ((tid & 31) < 8) red[wh][h] = sloc;
    __syncthreads();
    if (tid < NH1) ssv[tid] = 1.f / (red[0][tid] + red[1][tid]);
    __syncthreads();

    // ---- phase 2: gather (thread = output column), ELU ----
    {
        const int hh = tid >> 3;
        const float inv = ssv[hh];
        float a0 = 0.f, a1 = 0.f, a2 = 0.f, a3 = 0.f;
        int j = 0;
        for (; j + 4 <= deg; j += 4) {
            a0 += ew[(j+0) * NH1 + hh] * g_h1[(size_t)snbr[j+0] * HD1 + tid];
            a1 += ew[(j+1) * NH1 + hh] * g_h1[(size_t)snbr[j+1] * HD1 + tid];
            a2 += ew[(j+2) * NH1 + hh] * g_h1[(size_t)snbr[j+2] * HD1 + tid];
            a3 += ew[(j+3) * NH1 + hh] * g_h1[(size_t)snbr[j+3] * HD1 + tid];
        }
        for (; j < deg; j++)
            a0 += ew[j * NH1 + hh] * g_h1[(size_t)snbr[j] * HD1 + tid];
        float acc = ((a0 + a1) + (a2 + a3)) * inv;
        acc = (acc > 0.f) ? acc : expm1f(acc);   // ELU
        sa1[tid] = acc;
    }
    __syncthreads();

    // ---- phase 3: fused layer-2 row: h2[i,:] = sa1 @ W2 + es2/ed2 ----
    if (tid < C2) {
        float v = 0.f;
        #pragma unroll 8
        for (int k = 0; k < HD1; k++)
            v += sa1[k] * __ldg(&W2[k * C2 + tid]);
        g_h2[(size_t)i * C2 + tid] = v;

        float s = v * a2_src[tid];
        float d = v * a2_dst[tid];
        #pragma unroll
        for (int o = 8; o >= 1; o >>= 1) {
            s += __shfl_xor_sync(0x0000FFFFu, s, o);
            d += __shfl_xor_sync(0x0000FFFFu, d, o);
        }
        if (tid == 0) {
            g_es2[i] = s;
            g_ed2[i] = d;
        }
    }
}

// ---------------------------------------------------------------------------
// K3: layer-2 sparse attention. Single fused pass (round-11 best, unchanged).
// ---------------------------------------------------------------------------
__global__ __launch_bounds__(256) void k_attn2(float* __restrict__ out)
{
    const int w    = threadIdx.x >> 5;
    const int lane = threadIdx.x & 31;
    const int i    = blockIdx.x * 8 + w;
    const int deg  = g_deg[i];

    __shared__ int snbr[8][MAXDEG];

    for (int j = lane; j < deg; j += 32)
        snbr[w][j] = g_nbr[(size_t)i * MAXDEG + j];
    __syncwarp();

    const float esi = g_es2[i];
    const int g  = lane >> 2;
    const int c4 = lane & 3;

    float4 acc = make_float4(0.f, 0.f, 0.f, 0.f);
    float  wsum = 0.f;
    for (int base = 0; base < deg; base += 8) {
        int j = base + g;
        if (j < deg) {
            int   n  = snbr[w][j];
            float e  = esi + g_ed2[n];
            e = (e > 0.f) ? e : 0.2f * e;
            float wt = __expf(e);
            float4 v = *(const float4*)(g_h2 + (size_t)n * C2 + c4 * 4);
            acc.x += wt * v.x;
            acc.y += wt * v.y;
            acc.z += wt * v.z;
            acc.w += wt * v.w;
            wsum  += wt;
        }
    }
    #pragma unroll
    for (int o = 4; o <= 16; o <<= 1) {
        acc.x += __shfl_xor_sync(0xFFFFFFFFu, acc.x, o);
        acc.y += __shfl_xor_sync(0xFFFFFFFFu, acc.y, o);
        acc.z += __shfl_xor_sync(0xFFFFFFFFu, acc.z, o);
        acc.w += __shfl_xor_sync(0xFFFFFFFFu, acc.w, o);
        wsum  += __shfl_xor_sync(0xFFFFFFFFu, wsum,  o);
    }
    if (lane < 4) {
        const float inv = 1.f / wsum;
        float4 r = make_float4(acc.x * inv, acc.y * inv, acc.z * inv, acc.w * inv);
        *(float4*)(out + (size_t)i * C2 + lane * 4) = r;
    }
}

// ---------------------------------------------------------------------------
// Launch: strictly sequential on the capture stream. 3 kernels.
// ---------------------------------------------------------------------------
extern "C" void kernel_launch(void* const* d_in, const int* in_sizes, int n_in,
                              void* d_out, int out_size)
{
    const float* x      = (const float*)d_in[0];
    const void*  adj    = d_in[1];
    const float* W1     = (const float*)d_in[2];
    const float* a1_src = (const float*)d_in[3];
    const float* a1_dst = (const float*)d_in[4];
    const float* W2     = (const float*)d_in[5];
    const float* a2_src = (const float*)d_in[6];
    const float* a2_dst = (const float*)d_in[7];
    float* out = (float*)d_out;

    k_gemm1<<<N_NODES / 32, 256>>>(x, W1, a1_src, a1_dst);
    k_attn1<<<N_NODES, 64>>>(adj, W2, a2_src, a2_dst);
    k_attn2<<<N_NODES / 8, 256>>>(out);
}